// round 6
// baseline (speedup 1.0000x reference)
#include <cuda_runtime.h>
#include <cuda_bf16.h>
#include <cstdint>

// ---------------------------------------------------------------------------
//   image [16,3,256,256] -> conv1 s2 relu -> g_f1i [16,192,128,128] {hi,lo} u32
//   conv2 s2 relu (bf16x3 mma) -> g_f2i [16,384,64,64] {hi,lo} u32
//   conv3 s2      (bf16x3 mma) -> g_f3h/g_f3l [16384][768] bf16 planes
//   distance GEMM (bf16x3 mma) + fused argmax -> g_best
//   R6: (256,1) + full fragment double-buffer + 6-stage cp.async pipeline +
//       early gather-LDG issue. Fused cvt kernel (gemm0 back at launch #4).
// ---------------------------------------------------------------------------

__device__ uint32_t g_f1i[16u * 192u * 128u * 128u];
__device__ uint32_t g_f2i[16u * 384u * 64u * 64u];
__device__ __nv_bfloat16 g_f3h[16384u * 768u];
__device__ __nv_bfloat16 g_f3l[16384u * 768u];
__device__ __nv_bfloat16 g_w2h[384u * 1728u];
__device__ __nv_bfloat16 g_w2l[384u * 1728u];
__device__ __nv_bfloat16 g_w3h[768u * 3456u];
__device__ __nv_bfloat16 g_w3l[768u * 3456u];
__device__ __nv_bfloat16 g_cbh[8192u * 768u];
__device__ __nv_bfloat16 g_cbl[8192u * 768u];
__device__ float g_c2h[8192];
__device__ unsigned long long g_best[16384];

// ------------------------------ helpers -----------------------------------
__device__ __forceinline__ uint32_t smem_u32(const void* p) {
    uint32_t a;
    asm("{ .reg .u64 t; cvta.to.shared.u64 t, %1; cvt.u32.u64 %0, t; }"
        : "=r"(a) : "l"(p));
    return a;
}
__device__ __forceinline__ void ldsm4(uint32_t* r, uint32_t addr) {
    asm volatile("ldmatrix.sync.aligned.m8n8.x4.shared.b16 {%0,%1,%2,%3}, [%4];"
        : "=r"(r[0]), "=r"(r[1]), "=r"(r[2]), "=r"(r[3]) : "r"(addr));
}
__device__ __forceinline__ void mma_bf16(float* c, const uint32_t* a, const uint32_t* b) {
    asm volatile("mma.sync.aligned.m16n8k16.row.col.f32.bf16.bf16.f32 "
        "{%0,%1,%2,%3}, {%4,%5,%6,%7}, {%8,%9}, {%0,%1,%2,%3};"
        : "+f"(c[0]), "+f"(c[1]), "+f"(c[2]), "+f"(c[3])
        : "r"(a[0]), "r"(a[1]), "r"(a[2]), "r"(a[3]), "r"(b[0]), "r"(b[1]));
}
__device__ __forceinline__ uint32_t prmt(uint32_t a, uint32_t b, uint32_t c) {
    uint32_t d;
    asm("prmt.b32 %0, %1, %2, %3;" : "=r"(d) : "r"(a), "r"(b), "r"(c));
    return d;
}
__device__ __forceinline__ void cp16(uint32_t dst, const void* src) {
    asm volatile("cp.async.cg.shared.global [%0], [%1], 16;"
                 :: "r"(dst), "l"(src) : "memory");
}
__device__ __forceinline__ void sts128(uint32_t addr, uint32_t a, uint32_t b,
                                       uint32_t c, uint32_t d) {
    asm volatile("st.shared.v4.b32 [%0], {%1,%2,%3,%4};"
                 :: "r"(addr), "r"(a), "r"(b), "r"(c), "r"(d) : "memory");
}
__device__ __forceinline__ unsigned long long pack_key(float s, int v) {
    unsigned u = __float_as_uint(s);
    u = (u & 0x80000000u) ? ~u : (u | 0x80000000u);
    return ((unsigned long long)u << 32) | (unsigned)(0xFFFFFFFFu - (unsigned)v);
}
__device__ __forceinline__ uint32_t pack_hl(float v) {
    __nv_bfloat16 h = __float2bfloat16(v);
    float hf = __bfloat162float(h);
    __nv_bfloat16 l = __float2bfloat16(v - hf);
    return ((uint32_t)__bfloat16_as_ushort(l) << 16) | __bfloat16_as_ushort(h);
}

// ---------------------------------------------------------------------------
// bf16x3 mma GEMM. 128x128 tile, K-chunk 16, 6-stage cp.async pipeline,
// fragment double-buffer, early gather issue.
//  MODE 0: conv2  A=w2 planes, B=gather f1i, out f2i {hi,lo}+bias+relu
//  MODE 1: conv3  A=gather f2i, B=w3 planes, out f3 planes + bias
//  MODE 2: dist   A=f3 planes,  B=cb planes, fused argmax
// ---------------------------------------------------------------------------
static constexpr int TILE = 128 * 48;      // 6144 B
static constexpr int STAGE = 4 * TILE;     // Ah,Al,Bh,Bl = 24576 B
static constexpr int NSTAGE = 6;
static constexpr int GEMM_SMEM = NSTAGE * STAGE + 512;

#define WAITG(n) asm volatile("cp.async.wait_group %0;" :: "n"(n) : "memory")

template<int MODE>
__global__ __launch_bounds__(256, 1) void mma_gemm(
    const void* __restrict__ pa0, const void* __restrict__ pa1,
    const void* __restrict__ pb0, const void* __restrict__ pb1,
    const float* __restrict__ vec, void* __restrict__ o0,
    void* __restrict__ o1, int K)
{
    extern __shared__ char sm[];
    const uint32_t sb = smem_u32(sm);
    const int tid = threadIdx.x, wid = tid >> 5, lane = tid & 31;
    const int m0 = blockIdx.x * 128, n0 = blockIdx.y * 128;
    const int NT = K >> 4;                 // always even (48 / 108 / 216)

    float* vecs = (float*)(sm + NSTAGE * STAGE);
    if (tid < 128) vecs[tid] = vec[(MODE == 0 ? m0 : n0) + tid];

    const int lrow = tid >> 1, lhalf = tid & 1;

    // ---- source setup
    const char* dirA_h = nullptr; const char* dirA_l = nullptr;
    const char* dirB_h = nullptr; const char* dirB_l = nullptr;
    const uint32_t* gsrc = nullptr;
    int giy0 = 0, gix0 = 0;

    if constexpr (MODE == 0) {
        dirA_h = (const char*)pa0 + ((size_t)(m0 + lrow) * 1728 + lhalf * 8) * 2;
        dirA_l = (const char*)pa1 + ((size_t)(m0 + lrow) * 1728 + lhalf * 8) * 2;
        int n = n0 + lrow;
        int bb = n >> 12, rem = n & 4095;
        int oy = rem >> 6, ox = rem & 63;
        gsrc = (const uint32_t*)pb0 + (size_t)bb * (192u * 128u * 128u);
        giy0 = 2 * oy - 1; gix0 = 2 * ox - 1;
    } else if constexpr (MODE == 1) {
        int n = m0 + lrow;
        int bb = n >> 10, rem = n & 1023;
        int oy = rem >> 5, ox = rem & 31;
        gsrc = (const uint32_t*)pa0 + (size_t)bb * (384u * 64u * 64u);
        giy0 = 2 * oy - 1; gix0 = 2 * ox - 1;
        dirB_h = (const char*)pb0 + ((size_t)(n0 + lrow) * 3456 + lhalf * 8) * 2;
        dirB_l = (const char*)pb1 + ((size_t)(n0 + lrow) * 3456 + lhalf * 8) * 2;
    } else {
        dirA_h = (const char*)pa0 + ((size_t)(m0 + lrow) * 768 + lhalf * 8) * 2;
        dirA_l = (const char*)pa1 + ((size_t)(m0 + lrow) * 768 + lhalf * 8) * 2;
        dirB_h = (const char*)pb0 + ((size_t)(n0 + lrow) * 768 + lhalf * 8) * 2;
        dirB_l = (const char*)pb1 + ((size_t)(n0 + lrow) * 768 + lhalf * 8) * 2;
    }

    const uint32_t loff = (uint32_t)(lrow * 48 + lhalf * 16);
    uint32_t gregs[8];
    uint32_t gst_hi = 0, gst_lo = 0;       // pending gather STS targets

    // issue loads for chunk kt into stage s (cp.async committed; gather LDGs
    // land in gregs, STS deferred to finish())
    auto issue = [&](int kt, int s) {
        const uint32_t st = sb + (uint32_t)s * STAGE + loff;
        if constexpr (MODE == 0) {
            cp16(st,            dirA_h + kt * 32);
            cp16(st + TILE,     dirA_l + kt * 32);
        } else if constexpr (MODE == 1) {
            cp16(st + 2 * TILE, dirB_h + kt * 32);
            cp16(st + 3 * TILE, dirB_l + kt * 32);
        } else {
            cp16(st,            dirA_h + kt * 32);
            cp16(st + TILE,     dirA_l + kt * 32);
            cp16(st + 2 * TILE, dirB_h + kt * 32);
            cp16(st + 3 * TILE, dirB_l + kt * 32);
        }
        asm volatile("cp.async.commit_group;" ::: "memory");
        if constexpr (MODE == 0 || MODE == 1) {
            const int HIN = (MODE == 0) ? 128 : 64;
            const int k0 = kt * 16 + lhalf * 8;
#pragma unroll
            for (int j = 0; j < 8; j++) {
                int k = k0 + j;
                int ci = (k * 7282) >> 16;     // k/9
                int r = k - ci * 9;
                int ky = (r * 11) >> 5;        // r/3
                int kx = r - ky * 3;
                int iy = giy0 + ky, ix = gix0 + kx;
                bool ok = (iy >= 0) && (iy < HIN) && (ix >= 0) && (ix < HIN);
                gregs[j] = ok ? gsrc[(size_t)((ci * HIN + iy) * HIN + ix)] : 0u;
            }
            gst_hi = st + ((MODE == 0) ? 2 * TILE : 0);
            gst_lo = gst_hi + TILE;
        }
    };
    auto finish = [&]() {
        if constexpr (MODE == 0 || MODE == 1) {
            sts128(gst_hi, prmt(gregs[0], gregs[1], 0x5410), prmt(gregs[2], gregs[3], 0x5410),
                           prmt(gregs[4], gregs[5], 0x5410), prmt(gregs[6], gregs[7], 0x5410));
            sts128(gst_lo, prmt(gregs[0], gregs[1], 0x7632), prmt(gregs[2], gregs[3], 0x7632),
                           prmt(gregs[4], gregs[5], 0x7632), prmt(gregs[6], gregs[7], 0x7632));
        }
    };

    // ---- warp tiling: 2 (m) x 4 (n), each warp 64x32
    const int wm = wid & 1, wn = wid >> 1;
    const int q = lane >> 3, rr = lane & 7;
    const uint32_t a_off = (uint32_t)((wm * 64 + (q & 1) * 8 + rr) * 48 + (q >> 1) * 16);
    const uint32_t b_off = (uint32_t)(((q >> 1) * 8 + rr) * 48 + (q & 1) * 16)
                         + (uint32_t)(wn * 32) * 48;

    uint32_t fAh[2][4][4], fAl[2][4][4], fBh[2][2][4], fBl[2][2][4];

#define LDSM_FRAGS(B, sidx) do {                                               \
    const uint32_t _base = sb + (uint32_t)(sidx) * STAGE;                      \
    ldsm4(fBh[B][0], _base + 2 * TILE + b_off);                                \
    ldsm4(fBh[B][1], _base + 2 * TILE + b_off + 16 * 48);                      \
    ldsm4(fBl[B][0], _base + 3 * TILE + b_off);                                \
    ldsm4(fBl[B][1], _base + 3 * TILE + b_off + 16 * 48);                      \
    _Pragma("unroll")                                                          \
    for (int mi = 0; mi < 4; mi++) {                                           \
        ldsm4(fAh[B][mi], _base + a_off + mi * 768);                           \
        ldsm4(fAl[B][mi], _base + TILE + a_off + mi * 768);                    \
    }                                                                          \
} while (0)

#define MMA_ALL(B) do {                                                        \
    _Pragma("unroll")                                                          \
    for (int mi = 0; mi < 4; mi++) {                                           \
        _Pragma("unroll")                                                      \
        for (int nj = 0; nj < 4; nj++)                                         \
            mma_bf16(acc[mi][nj], fAh[B][mi], &fBh[B][nj >> 1][(nj & 1) * 2]); \
        _Pragma("unroll")                                                      \
        for (int nj = 0; nj < 4; nj++)                                         \
            mma_bf16(acc[mi][nj], fAh[B][mi], &fBl[B][nj >> 1][(nj & 1) * 2]); \
        _Pragma("unroll")                                                      \
        for (int nj = 0; nj < 4; nj++)                                         \
            mma_bf16(acc[mi][nj], fAl[B][mi], &fBh[B][nj >> 1][(nj & 1) * 2]); \
    }                                                                          \
} while (0)

    float acc[4][4][4];
#pragma unroll
    for (int i = 0; i < 4; i++)
#pragma unroll
        for (int j = 0; j < 4; j++)
#pragma unroll
            for (int e = 0; e < 4; e++) acc[i][j][e] = 0.f;

    // prologue: fill stages 0..4
#pragma unroll 1
    for (int j = 0; j < NSTAGE - 1; j++) { issue(j, j); finish(); }
    WAITG(4);
    __syncthreads();
    LDSM_FRAGS(0, 0);

    int s_ld = NSTAGE - 1;     // stage receiving chunk kt+5
    int s_c1 = 1;              // stage of chunk kt+1
#pragma unroll 1
    for (int kt = 0; kt < NT; kt += 2) {
        // --- half-iter A: compute chunk kt (buf 0), prefetch kt+1 (buf 1)
        {
            int ktl = kt + NSTAGE - 1; if (ktl > NT - 1) ktl = NT - 1;
            issue(ktl, s_ld); if (++s_ld == NSTAGE) s_ld = 0;
            WAITG(4);
            __syncthreads();
            LDSM_FRAGS(1, s_c1); if (++s_c1 == NSTAGE) s_c1 = 0;
            MMA_ALL(0);
            finish();
        }
        // --- half-iter B: compute chunk kt+1 (buf 1), prefetch kt+2 (buf 0)
        {
            int ktl = kt + NSTAGE; if (ktl > NT - 1) ktl = NT - 1;
            issue(ktl, s_ld); if (++s_ld == NSTAGE) s_ld = 0;
            if (kt + 2 < NT) {
                WAITG(4);
                __syncthreads();
                LDSM_FRAGS(0, s_c1); if (++s_c1 == NSTAGE) s_c1 = 0;
            }
            MMA_ALL(1);
            finish();
        }
    }
    WAITG(0);

    // ---- epilogue. Fragment c[e]: rows tg(+8), cols 2*tp + e%2
    const int tg = lane >> 2, tp = lane & 3;

    if constexpr (MODE == 0) {
        uint32_t* Ci = (uint32_t*)o0;
        const int bb = n0 >> 12;
        const int sp0 = (n0 & 4095) + wn * 32;
#pragma unroll
        for (int mi = 0; mi < 4; mi++)
#pragma unroll
            for (int h = 0; h < 2; h++) {
                int ml = wm * 64 + mi * 16 + tg + h * 8;
                int m = m0 + ml;
                float bv = vecs[ml];
                uint32_t* rowp = Ci + ((size_t)bb * 384 + m) * 4096;
#pragma unroll
                for (int nj = 0; nj < 4; nj++) {
                    float v0 = fmaxf(acc[mi][nj][h * 2 + 0] + bv, 0.f);
                    float v1 = fmaxf(acc[mi][nj][h * 2 + 1] + bv, 0.f);
                    *(uint2*)(rowp + sp0 + nj * 8 + 2 * tp) =
                        make_uint2(pack_hl(v0), pack_hl(v1));
                }
            }
    } else if constexpr (MODE == 1) {
        __nv_bfloat16* fh = (__nv_bfloat16*)o0;
        __nv_bfloat16* fl = (__nv_bfloat16*)o1;
#pragma unroll
        for (int mi = 0; mi < 4; mi++)
#pragma unroll
            for (int h = 0; h < 2; h++) {
                int m = m0 + wm * 64 + mi * 16 + tg + h * 8;   // token
                __nv_bfloat16* rowh = fh + (size_t)m * 768 + n0;
                __nv_bfloat16* rowl = fl + (size_t)m * 768 + n0;
#pragma unroll
                for (int nj = 0; nj < 4; nj++) {
                    int nl = wn * 32 + nj * 8 + 2 * tp;
                    float v0 = acc[mi][nj][h * 2 + 0] + vecs[nl + 0];
                    float v1 = acc[mi][nj][h * 2 + 1] + vecs[nl + 1];
                    __nv_bfloat16 h0 = __float2bfloat16(v0);
                    __nv_bfloat16 h1 = __float2bfloat16(v1);
                    __nv_bfloat16 l0 = __float2bfloat16(v0 - __bfloat162float(h0));
                    __nv_bfloat16 l1 = __float2bfloat16(v1 - __bfloat162float(h1));
                    *(__nv_bfloat162*)(rowh + nl) = __nv_bfloat162(h0, h1);
                    *(__nv_bfloat162*)(rowl + nl) = __nv_bfloat162(l0, l1);
                }
            }
    } else {
#pragma unroll
        for (int mi = 0; mi < 4; mi++)
#pragma unroll
            for (int h = 0; h < 2; h++) {
                int m = m0 + wm * 64 + mi * 16 + tg + h * 8;   // token
                unsigned long long best = 0ull;
#pragma unroll
                for (int nj = 0; nj < 4; nj++)
#pragma unroll
                    for (int e = 0; e < 2; e++) {
                        int nl = wn * 32 + nj * 8 + 2 * tp + e;
                        float sc = acc[mi][nj][h * 2 + e] - vecs[nl];
                        unsigned long long key = pack_key(sc, n0 + nl);
                        best = key > best ? key : best;
                    }
                unsigned long long o = __shfl_xor_sync(0xFFFFFFFFu, best, 1);
                best = best > o ? best : o;
                o = __shfl_xor_sync(0xFFFFFFFFu, best, 2);
                best = best > o ? best : o;
                if (tp == 0) atomicMax(&g_best[m], best);
            }
    }
#undef LDSM_FRAGS
#undef MMA_ALL
}

// ---------------------------------------------------------------------------
// conv1: Cin=3, 3x3 s2 pad1, relu -> interleaved {hi,lo} uint32 NCHW
// ---------------------------------------------------------------------------
__global__ __launch_bounds__(128) void conv1_kernel(
    const float* __restrict__ in, const float* __restrict__ w,
    const float* __restrict__ bias)
{
    __shared__ float Ws[192 * 27];
    __shared__ float Bsm[192];
    for (int i = threadIdx.x; i < 192 * 27; i += 128) Ws[i] = w[i];
    for (int i = threadIdx.x; i < 192; i += 128) Bsm[i] = bias[i];
    __syncthreads();

    int g = blockIdx.x * 128 + threadIdx.x;
    int x0 = (g & 31) * 4;
    int y = (g >> 5) & 127;
    int b = g >> 12;

    float xv[3][3][9];
    int iy0 = 2 * y - 1;
    int ix0 = 2 * x0 - 1;
#pragma unroll
    for (int ci = 0; ci < 3; ci++)
#pragma unroll
        for (int ky = 0; ky < 3; ky++) {
            int iy = iy0 + ky;
            bool yok = (iy >= 0) && (iy < 256);
            const float* rowp = in + (((size_t)b * 3 + ci) * 256 + iy) * 256;
#pragma unroll
            for (int c = 0; c < 9; c++) {
                int ix = ix0 + c;
                xv[ci][ky][c] = (yok && ix >= 0 && ix < 256) ? rowp[ix] : 0.f;
            }
        }

    uint32_t* outp = g_f1i + (size_t)b * 192 * 16384 + y * 128 + x0;
    for (int co = 0; co < 192; co++) {
        float bv = Bsm[co];
        float a0 = bv, a1 = bv, a2 = bv, a3 = bv;
        const float* wp = &Ws[co * 27];
#pragma unroll
        for (int ci = 0; ci < 3; ci++)
#pragma unroll
            for (int ky = 0; ky < 3; ky++)
#pragma unroll
                for (int kx = 0; kx < 3; kx++) {
                    float wv = wp[ci * 9 + ky * 3 + kx];
                    a0 = fmaf(wv, xv[ci][ky][0 + kx], a0);
                    a1 = fmaf(wv, xv[ci][ky][2 + kx], a1);
                    a2 = fmaf(wv, xv[ci][ky][4 + kx], a2);
                    a3 = fmaf(wv, xv[ci][ky][6 + kx], a3);
                }
        uint4 r;
        r.x = pack_hl(fmaxf(a0, 0.f));
        r.y = pack_hl(fmaxf(a1, 0.f));
        r.z = pack_hl(fmaxf(a2, 0.f));
        r.w = pack_hl(fmaxf(a3, 0.f));
        *(uint4*)(outp + (size_t)co * 16384) = r;
    }
}

// ---------------------------------------------------------------------------
// fused conversion of w2 / w3 / codebook to bf16 hi/lo planes (one launch)
static constexpr int N_W2 = 384 * 1728;
static constexpr int N_W3 = 768 * 3456;
static constexpr int N_CB = 8192 * 768;

__global__ void cvt_all_kernel(const float* __restrict__ w2,
                               const float* __restrict__ w3,
                               const float* __restrict__ cb)
{
    int i = blockIdx.x * 256 + threadIdx.x;
    const float* src; __nv_bfloat16 *hi, *lo; int idx;
    if (i < N_W2) { src = w2; hi = g_w2h; lo = g_w2l; idx = i; }
    else if (i < N_W2 + N_W3) { src = w3; hi = g_w3h; lo = g_w3l; idx = i - N_W2; }
    else if (i < N_W2 + N_W3 + N_CB) { src = cb; hi = g_cbh; lo = g_cbl; idx = i - N_W2 - N_W3; }
    else return;
    float v = src[idx];
    __nv_bfloat16 h = __float2bfloat16(v);
    hi[idx] = h;
    lo[idx] = __float2bfloat16(v - __bfloat162float(h));
}

// c2half + g_best init fused
__global__ void c2half_kernel(const float* __restrict__ cb) {
    int gt = blockIdx.x * 256 + threadIdx.x;
    if (gt < 16384) g_best[gt] = 0ULL;
    int v = blockIdx.x * 8 + (threadIdx.x >> 5);
    int lane = threadIdx.x & 31;
    const float* row = cb + (size_t)v * 768;
    float s = 0.f;
    for (int c = lane; c < 768; c += 32) { float t = row[c]; s = fmaf(t, t, s); }
#pragma unroll
    for (int o = 16; o > 0; o >>= 1) s += __shfl_xor_sync(0xFFFFFFFFu, s, o);
    if (lane == 0) g_c2h[v] = 0.5f * s;
}

__global__ __launch_bounds__(192) void output_kernel(
    const float* __restrict__ table, float* __restrict__ out)
{
    int p = blockIdx.x;
    unsigned long long key = g_best[p];
    unsigned v = 0xFFFFFFFFu - (unsigned)(key & 0xFFFFFFFFu);
    if (threadIdx.x == 0) out[p] = (float)v;
    float4* dst = (float4*)(out + 16384 + (size_t)p * 768);
    const float4* src = (const float4*)(table + (size_t)v * 768);
    dst[threadIdx.x] = src[threadIdx.x];
}

// ---------------------------------------------------------------------------
extern "C" void kernel_launch(void* const* d_in, const int* in_sizes, int n_in,
                              void* d_out, int out_size)
{
    (void)in_sizes; (void)n_in; (void)out_size;
    const float* image = (const float*)d_in[0];
    const float* w1 = (const float*)d_in[1];
    const float* b1 = (const float*)d_in[2];
    const float* w2 = (const float*)d_in[3];
    const float* b2 = (const float*)d_in[4];
    const float* w3 = (const float*)d_in[5];
    const float* b3 = (const float*)d_in[6];
    const float* cb = (const float*)d_in[7];
    const float* tab = (const float*)d_in[8];
    float* out = (float*)d_out;

    void *pf1, *pf2, *pf3h, *pf3l, *pw2h, *pw2l, *pw3h, *pw3l, *pcbh, *pcbl, *pc2;
    cudaGetSymbolAddress(&pf1, g_f1i);
    cudaGetSymbolAddress(&pf2, g_f2i);
    cudaGetSymbolAddress(&pf3h, g_f3h);
    cudaGetSymbolAddress(&pf3l, g_f3l);
    cudaGetSymbolAddress(&pw2h, g_w2h);
    cudaGetSymbolAddress(&pw2l, g_w2l);
    cudaGetSymbolAddress(&pw3h, g_w3h);
    cudaGetSymbolAddress(&pw3l, g_w3l);
    cudaGetSymbolAddress(&pcbh, g_cbh);
    cudaGetSymbolAddress(&pcbl, g_cbl);
    cudaGetSymbolAddress(&pc2, g_c2h);

    cudaFuncSetAttribute(mma_gemm<0>, cudaFuncAttributeMaxDynamicSharedMemorySize, GEMM_SMEM);
    cudaFuncSetAttribute(mma_gemm<1>, cudaFuncAttributeMaxDynamicSharedMemorySize, GEMM_SMEM);
    cudaFuncSetAttribute(mma_gemm<2>, cudaFuncAttributeMaxDynamicSharedMemorySize, GEMM_SMEM);

    c2half_kernel<<<1024, 256>>>(cb);
    cvt_all_kernel<<<(N_W2 + N_W3 + N_CB + 255) / 256, 256>>>(w2, w3, cb);
    conv1_kernel<<<512, 128>>>(image, w1, b1);

    // conv2: M=384 (w2 rows), N=65536 (spatial), K=1728
    mma_gemm<0><<<dim3(3, 512), 256, GEMM_SMEM>>>(
        pw2h, pw2l, pf1, nullptr, b2, pf2, nullptr, 1728);
    // conv3: M=16384 (tokens, gathered), N=768 (w3 rows), K=3456
    mma_gemm<1><<<dim3(128, 6), 256, GEMM_SMEM>>>(
        pf2, nullptr, pw3h, pw3l, b3, pf3h, pf3l, 3456);
    // distance: M=16384 (tokens), N=8192 (codes), K=768, fused argmax
    mma_gemm<2><<<dim3(128, 64), 256, GEMM_SMEM>>>(
        pf3h, pf3l, pcbh, pcbl, (const float*)pc2, nullptr, nullptr, 768);

    output_kernel<<<16384, 192>>>(tab, out);
}

// round 7
// speedup vs baseline: 1.1699x; 1.1699x over previous
#include <cuda_runtime.h>
#include <cuda_bf16.h>
#include <cstdint>

// ---------------------------------------------------------------------------
//   image [16,3,256,256] -> conv1 s2 relu -> g_f1i [16,192,128,128] {hi,lo} u32
//   conv2 s2 relu (bf16x3 mma) -> g_f2i [16,384,64,64] {hi,lo} u32
//   conv3 s2      (bf16x3 mma) -> g_f3h/g_f3l [16384][768] bf16 planes
//   distance GEMM (bf16x3 mma) + fused argmax -> g_best
//   R7: warp tile 64x64 (4 warps / 128 threads per CTA) -> smem bytes per MMA
//       drop 1.5x (LDS-BW was the binding limit). 2 CTAs/SM kept.
// ---------------------------------------------------------------------------

__device__ uint32_t g_f1i[16u * 192u * 128u * 128u];
__device__ uint32_t g_f2i[16u * 384u * 64u * 64u];
__device__ __nv_bfloat16 g_f3h[16384u * 768u];
__device__ __nv_bfloat16 g_f3l[16384u * 768u];
__device__ __nv_bfloat16 g_w2h[384u * 1728u];
__device__ __nv_bfloat16 g_w2l[384u * 1728u];
__device__ __nv_bfloat16 g_w3h[768u * 3456u];
__device__ __nv_bfloat16 g_w3l[768u * 3456u];
__device__ __nv_bfloat16 g_cbh[8192u * 768u];
__device__ __nv_bfloat16 g_cbl[8192u * 768u];
__device__ float g_c2h[8192];
__device__ unsigned long long g_best[16384];

// ------------------------------ helpers -----------------------------------
__device__ __forceinline__ uint32_t smem_u32(const void* p) {
    uint32_t a;
    asm("{ .reg .u64 t; cvta.to.shared.u64 t, %1; cvt.u32.u64 %0, t; }"
        : "=r"(a) : "l"(p));
    return a;
}
__device__ __forceinline__ void ldsm4(uint32_t* r, uint32_t addr) {
    asm volatile("ldmatrix.sync.aligned.m8n8.x4.shared.b16 {%0,%1,%2,%3}, [%4];"
        : "=r"(r[0]), "=r"(r[1]), "=r"(r[2]), "=r"(r[3]) : "r"(addr));
}
__device__ __forceinline__ void mma_bf16(float* c, const uint32_t* a, const uint32_t* b) {
    asm volatile("mma.sync.aligned.m16n8k16.row.col.f32.bf16.bf16.f32 "
        "{%0,%1,%2,%3}, {%4,%5,%6,%7}, {%8,%9}, {%0,%1,%2,%3};"
        : "+f"(c[0]), "+f"(c[1]), "+f"(c[2]), "+f"(c[3])
        : "r"(a[0]), "r"(a[1]), "r"(a[2]), "r"(a[3]), "r"(b[0]), "r"(b[1]));
}
__device__ __forceinline__ uint32_t prmt(uint32_t a, uint32_t b, uint32_t c) {
    uint32_t d;
    asm("prmt.b32 %0, %1, %2, %3;" : "=r"(d) : "r"(a), "r"(b), "r"(c));
    return d;
}
__device__ __forceinline__ void cp16(uint32_t dst, const void* src) {
    asm volatile("cp.async.cg.shared.global [%0], [%1], 16;"
                 :: "r"(dst), "l"(src) : "memory");
}
__device__ __forceinline__ void sts128(uint32_t addr, uint32_t a, uint32_t b,
                                       uint32_t c, uint32_t d) {
    asm volatile("st.shared.v4.b32 [%0], {%1,%2,%3,%4};"
                 :: "r"(addr), "r"(a), "r"(b), "r"(c), "r"(d) : "memory");
}
__device__ __forceinline__ unsigned long long pack_key(float s, int v) {
    unsigned u = __float_as_uint(s);
    u = (u & 0x80000000u) ? ~u : (u | 0x80000000u);
    return ((unsigned long long)u << 32) | (unsigned)(0xFFFFFFFFu - (unsigned)v);
}
__device__ __forceinline__ uint32_t pack_hl(float v) {
    __nv_bfloat16 h = __float2bfloat16(v);
    float hf = __bfloat162float(h);
    __nv_bfloat16 l = __float2bfloat16(v - hf);
    return ((uint32_t)__bfloat16_as_ushort(l) << 16) | __bfloat16_as_ushort(h);
}

// ---------------------------------------------------------------------------
// bf16x3 mma GEMM. 128x128 CTA tile, 4 warps (2x2) of 64x64, K-chunk 16,
// 4-stage cp.async. Gather LDGs issue before MMA block, STS after.
//  MODE 0: conv2  A=w2 planes, B=gather f1i, out f2i {hi,lo}+bias+relu
//  MODE 1: conv3  A=gather f2i, B=w3 planes, out f3 planes + bias
//  MODE 2: dist   A=f3 planes,  B=cb planes, fused argmax
// ---------------------------------------------------------------------------
static constexpr int TILE = 128 * 48;      // 6144 B (one plane, 128 rows)
static constexpr int STAGE = 4 * TILE;     // Ah,Al,Bh,Bl = 24576 B
static constexpr int NSTAGE = 4;
static constexpr int GEMM_SMEM = NSTAGE * STAGE + 512;

#define WAITG(n) asm volatile("cp.async.wait_group %0;" :: "n"(n) : "memory")

template<int MODE>
__global__ __launch_bounds__(128, 2) void mma_gemm(
    const void* __restrict__ pa0, const void* __restrict__ pa1,
    const void* __restrict__ pb0, const void* __restrict__ pb1,
    const float* __restrict__ vec, void* __restrict__ o0,
    void* __restrict__ o1, int K)
{
    extern __shared__ char sm[];
    const uint32_t sb = smem_u32(sm);
    const int tid = threadIdx.x, wid = tid >> 5, lane = tid & 31;
    const int m0 = blockIdx.x * 128, n0 = blockIdx.y * 128;
    const int NT = K >> 4;

    float* vecs = (float*)(sm + NSTAGE * STAGE);
    vecs[tid] = vec[(MODE == 0 ? m0 : n0) + tid];

    // ---- source setup: thread t owns A row t and B row t (32B per plane/chunk)
    const char* dirA_h = nullptr; const char* dirA_l = nullptr;
    const char* dirB_h = nullptr; const char* dirB_l = nullptr;
    const uint32_t* gsrc = nullptr;
    int giy0 = 0, gix0 = 0;

    if constexpr (MODE == 0) {
        dirA_h = (const char*)pa0 + (size_t)(m0 + tid) * 1728 * 2;
        dirA_l = (const char*)pa1 + (size_t)(m0 + tid) * 1728 * 2;
        int n = n0 + tid;
        int bb = n >> 12, rem = n & 4095;
        int oy = rem >> 6, ox = rem & 63;
        gsrc = (const uint32_t*)pb0 + (size_t)bb * (192u * 128u * 128u);
        giy0 = 2 * oy - 1; gix0 = 2 * ox - 1;
    } else if constexpr (MODE == 1) {
        int n = m0 + tid;
        int bb = n >> 10, rem = n & 1023;
        int oy = rem >> 5, ox = rem & 31;
        gsrc = (const uint32_t*)pa0 + (size_t)bb * (384u * 64u * 64u);
        giy0 = 2 * oy - 1; gix0 = 2 * ox - 1;
        dirB_h = (const char*)pb0 + (size_t)(n0 + tid) * 3456 * 2;
        dirB_l = (const char*)pb1 + (size_t)(n0 + tid) * 3456 * 2;
    } else {
        dirA_h = (const char*)pa0 + (size_t)(m0 + tid) * 768 * 2;
        dirA_l = (const char*)pa1 + (size_t)(m0 + tid) * 768 * 2;
        dirB_h = (const char*)pb0 + (size_t)(n0 + tid) * 768 * 2;
        dirB_l = (const char*)pb1 + (size_t)(n0 + tid) * 768 * 2;
    }

    const uint32_t loff = (uint32_t)tid * 48;
    uint32_t gregs[16];
    uint32_t gst_hi = 0, gst_lo = 0;

    // issue direct cp.async + gather LDGs for chunk kt into stage s
    auto issue = [&](int kt, int s) {
        const uint32_t st = sb + (uint32_t)s * STAGE + loff;
        if constexpr (MODE == 0) {
            cp16(st,                  dirA_h + kt * 32);
            cp16(st + 16,             dirA_h + kt * 32 + 16);
            cp16(st + TILE,           dirA_l + kt * 32);
            cp16(st + TILE + 16,      dirA_l + kt * 32 + 16);
        } else if constexpr (MODE == 1) {
            cp16(st + 2 * TILE,       dirB_h + kt * 32);
            cp16(st + 2 * TILE + 16,  dirB_h + kt * 32 + 16);
            cp16(st + 3 * TILE,       dirB_l + kt * 32);
            cp16(st + 3 * TILE + 16,  dirB_l + kt * 32 + 16);
        } else {
            cp16(st,                  dirA_h + kt * 32);
            cp16(st + 16,             dirA_h + kt * 32 + 16);
            cp16(st + TILE,           dirA_l + kt * 32);
            cp16(st + TILE + 16,      dirA_l + kt * 32 + 16);
            cp16(st + 2 * TILE,       dirB_h + kt * 32);
            cp16(st + 2 * TILE + 16,  dirB_h + kt * 32 + 16);
            cp16(st + 3 * TILE,       dirB_l + kt * 32);
            cp16(st + 3 * TILE + 16,  dirB_l + kt * 32 + 16);
        }
        asm volatile("cp.async.commit_group;" ::: "memory");
        if constexpr (MODE == 0 || MODE == 1) {
            const int HIN = (MODE == 0) ? 128 : 64;
            const int k0 = kt * 16;
#pragma unroll
            for (int j = 0; j < 16; j++) {
                int k = k0 + j;
                int ci = (k * 7282) >> 16;     // k/9
                int r = k - ci * 9;
                int ky = (r * 11) >> 5;        // r/3
                int kx = r - ky * 3;
                int iy = giy0 + ky, ix = gix0 + kx;
                bool ok = (iy >= 0) && (iy < HIN) && (ix >= 0) && (ix < HIN);
                gregs[j] = ok ? gsrc[(size_t)((ci * HIN + iy) * HIN + ix)] : 0u;
            }
            gst_hi = st + ((MODE == 0) ? 2 * TILE : 0);
            gst_lo = gst_hi + TILE;
        }
    };
    auto finish = [&]() {
        if constexpr (MODE == 0 || MODE == 1) {
            sts128(gst_hi,      prmt(gregs[0],  gregs[1],  0x5410), prmt(gregs[2],  gregs[3],  0x5410),
                                prmt(gregs[4],  gregs[5],  0x5410), prmt(gregs[6],  gregs[7],  0x5410));
            sts128(gst_hi + 16, prmt(gregs[8],  gregs[9],  0x5410), prmt(gregs[10], gregs[11], 0x5410),
                                prmt(gregs[12], gregs[13], 0x5410), prmt(gregs[14], gregs[15], 0x5410));
            sts128(gst_lo,      prmt(gregs[0],  gregs[1],  0x7632), prmt(gregs[2],  gregs[3],  0x7632),
                                prmt(gregs[4],  gregs[5],  0x7632), prmt(gregs[6],  gregs[7],  0x7632));
            sts128(gst_lo + 16, prmt(gregs[8],  gregs[9],  0x7632), prmt(gregs[10], gregs[11], 0x7632),
                                prmt(gregs[12], gregs[13], 0x7632), prmt(gregs[14], gregs[15], 0x7632));
        }
    };

    // ---- warp tiling: 2 (m) x 2 (n), each warp 64x64
    const int wm = wid & 1, wn = wid >> 1;
    const int q = lane >> 3, rr = lane & 7;
    const uint32_t a_off = (uint32_t)((wm * 64 + (q & 1) * 8 + rr) * 48 + (q >> 1) * 16);
    const uint32_t b_off = (uint32_t)(((q >> 1) * 8 + rr) * 48 + (q & 1) * 16)
                         + (uint32_t)(wn * 64) * 48;

    float acc[4][8][4];
#pragma unroll
    for (int i = 0; i < 4; i++)
#pragma unroll
        for (int j = 0; j < 8; j++)
#pragma unroll
            for (int e = 0; e < 4; e++) acc[i][j][e] = 0.f;

    // prologue
    issue(0, 0); finish();
    issue(1, 1); finish();
    issue(2, 2); finish();

#pragma unroll 1
    for (int kt = 0; kt < NT; kt++) {
        if (kt + 2 < NT)      WAITG(2);
        else if (kt + 1 < NT) WAITG(1);
        else                  WAITG(0);
        __syncthreads();

        const int s = kt & 3;
        const uint32_t Ah_b = sb + s * STAGE;
        const uint32_t Al_b = Ah_b + TILE;
        const uint32_t Bh_b = Ah_b + 2 * TILE;
        const uint32_t Bl_b = Ah_b + 3 * TILE;

        uint32_t Bh[4][4], Bl[4][4];
#pragma unroll
        for (int ni = 0; ni < 4; ni++) {
            ldsm4(Bh[ni], Bh_b + b_off + ni * 16 * 48);
            ldsm4(Bl[ni], Bl_b + b_off + ni * 16 * 48);
        }

        // start next chunk's global loads now; their STS happens after MMA
        const bool doNext = (kt + 3 < NT);
        if (doNext) issue(kt + 3, (kt + 3) & 3);

#pragma unroll
        for (int mi = 0; mi < 4; mi++) {
            uint32_t Ah[4], Al[4];
            ldsm4(Ah, Ah_b + a_off + mi * 768);
            ldsm4(Al, Al_b + a_off + mi * 768);
#pragma unroll
            for (int nj = 0; nj < 8; nj++)
                mma_bf16(acc[mi][nj], Ah, &Bh[nj >> 1][(nj & 1) * 2]);   // hi*hi
#pragma unroll
            for (int nj = 0; nj < 8; nj++)
                mma_bf16(acc[mi][nj], Ah, &Bl[nj >> 1][(nj & 1) * 2]);   // hi*lo
#pragma unroll
            for (int nj = 0; nj < 8; nj++)
                mma_bf16(acc[mi][nj], Al, &Bh[nj >> 1][(nj & 1) * 2]);   // lo*hi
        }

        if (doNext) finish();
    }

    // ---- epilogue. Fragment c[e]: rows tg(+8), cols 2*tp + e%2
    const int tg = lane >> 2, tp = lane & 3;

    if constexpr (MODE == 0) {
        uint32_t* Ci = (uint32_t*)o0;
        const int bb = n0 >> 12;
        const int sp0 = (n0 & 4095) + wn * 64;
#pragma unroll
        for (int mi = 0; mi < 4; mi++)
#pragma unroll
            for (int h = 0; h < 2; h++) {
                int ml = wm * 64 + mi * 16 + tg + h * 8;
                int m = m0 + ml;
                float bv = vecs[ml];
                uint32_t* rowp = Ci + ((size_t)bb * 384 + m) * 4096;
#pragma unroll
                for (int nj = 0; nj < 8; nj++) {
                    float v0 = fmaxf(acc[mi][nj][h * 2 + 0] + bv, 0.f);
                    float v1 = fmaxf(acc[mi][nj][h * 2 + 1] + bv, 0.f);
                    *(uint2*)(rowp + sp0 + nj * 8 + 2 * tp) =
                        make_uint2(pack_hl(v0), pack_hl(v1));
                }
            }
    } else if constexpr (MODE == 1) {
        __nv_bfloat16* fh = (__nv_bfloat16*)o0;
        __nv_bfloat16* fl = (__nv_bfloat16*)o1;
#pragma unroll
        for (int mi = 0; mi < 4; mi++)
#pragma unroll
            for (int h = 0; h < 2; h++) {
                int m = m0 + wm * 64 + mi * 16 + tg + h * 8;   // token
                __nv_bfloat16* rowh = fh + (size_t)m * 768 + n0;
                __nv_bfloat16* rowl = fl + (size_t)m * 768 + n0;
#pragma unroll
                for (int nj = 0; nj < 8; nj++) {
                    int nl = wn * 64 + nj * 8 + 2 * tp;
                    float v0 = acc[mi][nj][h * 2 + 0] + vecs[nl + 0];
                    float v1 = acc[mi][nj][h * 2 + 1] + vecs[nl + 1];
                    __nv_bfloat16 h0 = __float2bfloat16(v0);
                    __nv_bfloat16 h1 = __float2bfloat16(v1);
                    __nv_bfloat16 l0 = __float2bfloat16(v0 - __bfloat162float(h0));
                    __nv_bfloat16 l1 = __float2bfloat16(v1 - __bfloat162float(h1));
                    *(__nv_bfloat162*)(rowh + nl) = __nv_bfloat162(h0, h1);
                    *(__nv_bfloat162*)(rowl + nl) = __nv_bfloat162(l0, l1);
                }
            }
    } else {
#pragma unroll
        for (int mi = 0; mi < 4; mi++)
#pragma unroll
            for (int h = 0; h < 2; h++) {
                int m = m0 + wm * 64 + mi * 16 + tg + h * 8;   // token
                unsigned long long best = 0ull;
#pragma unroll
                for (int nj = 0; nj < 8; nj++)
#pragma unroll
                    for (int e = 0; e < 2; e++) {
                        int nl = wn * 64 + nj * 8 + 2 * tp + e;
                        float sc = acc[mi][nj][h * 2 + e] - vecs[nl];
                        unsigned long long key = pack_key(sc, n0 + nl);
                        best = key > best ? key : best;
                    }
                unsigned long long o = __shfl_xor_sync(0xFFFFFFFFu, best, 1);
                best = best > o ? best : o;
                o = __shfl_xor_sync(0xFFFFFFFFu, best, 2);
                best = best > o ? best : o;
                if (tp == 0) atomicMax(&g_best[m], best);
            }
    }
}

// ---------------------------------------------------------------------------
// conv1: Cin=3, 3x3 s2 pad1, relu -> interleaved {hi,lo} uint32 NCHW
// ---------------------------------------------------------------------------
__global__ __launch_bounds__(128) void conv1_kernel(
    const float* __restrict__ in, const float* __restrict__ w,
    const float* __restrict__ bias)
{
    __shared__ float Ws[192 * 27];
    __shared__ float Bsm[192];
    for (int i = threadIdx.x; i < 192 * 27; i += 128) Ws[i] = w[i];
    for (int i = threadIdx.x; i < 192; i += 128) Bsm[i] = bias[i];
    __syncthreads();

    int g = blockIdx.x * 128 + threadIdx.x;
    int x0 = (g & 31) * 4;
    int y = (g >> 5) & 127;
    int b = g >> 12;

    float xv[3][3][9];
    int iy0 = 2 * y - 1;
    int ix0 = 2 * x0 - 1;
#pragma unroll
    for (int ci = 0; ci < 3; ci++)
#pragma unroll
        for (int ky = 0; ky < 3; ky++) {
            int iy = iy0 + ky;
            bool yok = (iy >= 0) && (iy < 256);
            const float* rowp = in + (((size_t)b * 3 + ci) * 256 + iy) * 256;
#pragma unroll
            for (int c = 0; c < 9; c++) {
                int ix = ix0 + c;
                xv[ci][ky][c] = (yok && ix >= 0 && ix < 256) ? rowp[ix] : 0.f;
            }
        }

    uint32_t* outp = g_f1i + (size_t)b * 192 * 16384 + y * 128 + x0;
    for (int co = 0; co < 192; co++) {
        float bv = Bsm[co];
        float a0 = bv, a1 = bv, a2 = bv, a3 = bv;
        const float* wp = &Ws[co * 27];
#pragma unroll
        for (int ci = 0; ci < 3; ci++)
#pragma unroll
            for (int ky = 0; ky < 3; ky++)
#pragma unroll
                for (int kx = 0; kx < 3; kx++) {
                    float wv = wp[ci * 9 + ky * 3 + kx];
                    a0 = fmaf(wv, xv[ci][ky][0 + kx], a0);
                    a1 = fmaf(wv, xv[ci][ky][2 + kx], a1);
                    a2 = fmaf(wv, xv[ci][ky][4 + kx], a2);
                    a3 = fmaf(wv, xv[ci][ky][6 + kx], a3);
                }
        uint4 r;
        r.x = pack_hl(fmaxf(a0, 0.f));
        r.y = pack_hl(fmaxf(a1, 0.f));
        r.z = pack_hl(fmaxf(a2, 0.f));
        r.w = pack_hl(fmaxf(a3, 0.f));
        *(uint4*)(outp + (size_t)co * 16384) = r;
    }
}

// ---------------------------------------------------------------------------
static constexpr int N_W2 = 384 * 1728;
static constexpr int N_W3 = 768 * 3456;
static constexpr int N_CB = 8192 * 768;

__global__ void cvt_all_kernel(const float* __restrict__ w2,
                               const float* __restrict__ w3,
                               const float* __restrict__ cb)
{
    int i = blockIdx.x * 256 + threadIdx.x;
    const float* src; __nv_bfloat16 *hi, *lo; int idx;
    if (i < N_W2) { src = w2; hi = g_w2h; lo = g_w2l; idx = i; }
    else if (i < N_W2 + N_W3) { src = w3; hi = g_w3h; lo = g_w3l; idx = i - N_W2; }
    else if (i < N_W2 + N_W3 + N_CB) { src = cb; hi = g_cbh; lo = g_cbl; idx = i - N_W2 - N_W3; }
    else return;
    float v = src[idx];
    __nv_bfloat16 h = __float2bfloat16(v);
    hi[idx] = h;
    lo[idx] = __float2bfloat16(v - __bfloat162float(h));
}

// c2half + g_best init fused
__global__ void c2half_kernel(const float* __restrict__ cb) {
    int gt = blockIdx.x * 256 + threadIdx.x;
    if (gt < 16384) g_best[gt] = 0ULL;
    int v = blockIdx.x * 8 + (threadIdx.x >> 5);
    int lane = threadIdx.x & 31;
    const float* row = cb + (size_t)v * 768;
    float s = 0.f;
    for (int c = lane; c < 768; c += 32) { float t = row[c]; s = fmaf(t, t, s); }
#pragma unroll
    for (int o = 16; o > 0; o >>= 1) s += __shfl_xor_sync(0xFFFFFFFFu, s, o);
    if (lane == 0) g_c2h[v] = 0.5f * s;
}

__global__ __launch_bounds__(192) void output_kernel(
    const float* __restrict__ table, float* __restrict__ out)
{
    int p = blockIdx.x;
    unsigned long long key = g_best[p];
    unsigned v = 0xFFFFFFFFu - (unsigned)(key & 0xFFFFFFFFu);
    if (threadIdx.x == 0) out[p] = (float)v;
    float4* dst = (float4*)(out + 16384 + (size_t)p * 768);
    const float4* src = (const float4*)(table + (size_t)v * 768);
    dst[threadIdx.x] = src[threadIdx.x];
}

// ---------------------------------------------------------------------------
extern "C" void kernel_launch(void* const* d_in, const int* in_sizes, int n_in,
                              void* d_out, int out_size)
{
    (void)in_sizes; (void)n_in; (void)out_size;
    const float* image = (const float*)d_in[0];
    const float* w1 = (const float*)d_in[1];
    const float* b1 = (const float*)d_in[2];
    const float* w2 = (const float*)d_in[3];
    const float* b2 = (const float*)d_in[4];
    const float* w3 = (const float*)d_in[5];
    const float* b3 = (const float*)d_in[6];
    const float* cb = (const float*)d_in[7];
    const float* tab = (const float*)d_in[8];
    float* out = (float*)d_out;

    void *pf1, *pf2, *pf3h, *pf3l, *pw2h, *pw2l, *pw3h, *pw3l, *pcbh, *pcbl, *pc2;
    cudaGetSymbolAddress(&pf1, g_f1i);
    cudaGetSymbolAddress(&pf2, g_f2i);
    cudaGetSymbolAddress(&pf3h, g_f3h);
    cudaGetSymbolAddress(&pf3l, g_f3l);
    cudaGetSymbolAddress(&pw2h, g_w2h);
    cudaGetSymbolAddress(&pw2l, g_w2l);
    cudaGetSymbolAddress(&pw3h, g_w3h);
    cudaGetSymbolAddress(&pw3l, g_w3l);
    cudaGetSymbolAddress(&pcbh, g_cbh);
    cudaGetSymbolAddress(&pcbl, g_cbl);
    cudaGetSymbolAddress(&pc2, g_c2h);

    cudaFuncSetAttribute(mma_gemm<0>, cudaFuncAttributeMaxDynamicSharedMemorySize, GEMM_SMEM);
    cudaFuncSetAttribute(mma_gemm<1>, cudaFuncAttributeMaxDynamicSharedMemorySize, GEMM_SMEM);
    cudaFuncSetAttribute(mma_gemm<2>, cudaFuncAttributeMaxDynamicSharedMemorySize, GEMM_SMEM);

    c2half_kernel<<<1024, 256>>>(cb);
    cvt_all_kernel<<<(N_W2 + N_W3 + N_CB + 255) / 256, 256>>>(w2, w3, cb);
    conv1_kernel<<<512, 128>>>(image, w1, b1);

    // conv2: M=384 (w2 rows), N=65536 (spatial), K=1728
    mma_gemm<0><<<dim3(3, 512), 128, GEMM_SMEM>>>(
        pw2h, pw2l, pf1, nullptr, b2, pf2, nullptr, 1728);
    // conv3: M=16384 (tokens, gathered), N=768 (w3 rows), K=3456
    mma_gemm<1><<<dim3(128, 6), 128, GEMM_SMEM>>>(
        pf2, nullptr, pw3h, pw3l, b3, pf3h, pf3l, 3456);
    // distance: M=16384 (tokens), N=8192 (codes), K=768, fused argmax
    mma_gemm<2><<<dim3(128, 64), 128, GEMM_SMEM>>>(
        pf3h, pf3l, pcbh, pcbl, (const float*)pc2, nullptr, nullptr, 768);

    output_kernel<<<16384, 192>>>(tab, out);
}

// round 8
// speedup vs baseline: 1.2668x; 1.0828x over previous
#include <cuda_runtime.h>
#include <cuda_bf16.h>
#include <cstdint>

// ---------------------------------------------------------------------------
//   image [16,3,256,256] -> conv1 s2 relu -> g_f1i [16,192,128,128] {hi,lo} u32
//   conv2 s2 relu (WIDE bf16x3 mma) -> g_f2i [16,384,64,64] {hi,lo} u32
//   conv3 s2      (NARROW bf16x3 mma) -> g_f3h/g_f3l [16384][768] bf16 planes
//   distance GEMM (NARROW bf16x3 mma) + fused argmax -> g_best
//   R8: per-mode configs. WIDE = R7 64x64-warp kernel (measured 870us on conv2),
//       NARROW = R5 64x32-warp 16-warp/SM kernel (best for conv3/dist).
// ---------------------------------------------------------------------------

__device__ uint32_t g_f1i[16u * 192u * 128u * 128u];
__device__ uint32_t g_f2i[16u * 384u * 64u * 64u];
__device__ __nv_bfloat16 g_f3h[16384u * 768u];
__device__ __nv_bfloat16 g_f3l[16384u * 768u];
__device__ __nv_bfloat16 g_w2h[384u * 1728u];
__device__ __nv_bfloat16 g_w2l[384u * 1728u];
__device__ __nv_bfloat16 g_w3h[768u * 3456u];
__device__ __nv_bfloat16 g_w3l[768u * 3456u];
__device__ __nv_bfloat16 g_cbh[8192u * 768u];
__device__ __nv_bfloat16 g_cbl[8192u * 768u];
__device__ float g_c2h[8192];
__device__ unsigned long long g_best[16384];

// ------------------------------ helpers -----------------------------------
__device__ __forceinline__ uint32_t smem_u32(const void* p) {
    uint32_t a;
    asm("{ .reg .u64 t; cvta.to.shared.u64 t, %1; cvt.u32.u64 %0, t; }"
        : "=r"(a) : "l"(p));
    return a;
}
__device__ __forceinline__ void ldsm4(uint32_t* r, uint32_t addr) {
    asm volatile("ldmatrix.sync.aligned.m8n8.x4.shared.b16 {%0,%1,%2,%3}, [%4];"
        : "=r"(r[0]), "=r"(r[1]), "=r"(r[2]), "=r"(r[3]) : "r"(addr));
}
__device__ __forceinline__ void mma_bf16(float* c, const uint32_t* a, const uint32_t* b) {
    asm volatile("mma.sync.aligned.m16n8k16.row.col.f32.bf16.bf16.f32 "
        "{%0,%1,%2,%3}, {%4,%5,%6,%7}, {%8,%9}, {%0,%1,%2,%3};"
        : "+f"(c[0]), "+f"(c[1]), "+f"(c[2]), "+f"(c[3])
        : "r"(a[0]), "r"(a[1]), "r"(a[2]), "r"(a[3]), "r"(b[0]), "r"(b[1]));
}
__device__ __forceinline__ uint32_t prmt(uint32_t a, uint32_t b, uint32_t c) {
    uint32_t d;
    asm("prmt.b32 %0, %1, %2, %3;" : "=r"(d) : "r"(a), "r"(b), "r"(c));
    return d;
}
__device__ __forceinline__ void cp16(uint32_t dst, const void* src) {
    asm volatile("cp.async.cg.shared.global [%0], [%1], 16;"
                 :: "r"(dst), "l"(src) : "memory");
}
__device__ __forceinline__ void sts128(uint32_t addr, uint32_t a, uint32_t b,
                                       uint32_t c, uint32_t d) {
    asm volatile("st.shared.v4.b32 [%0], {%1,%2,%3,%4};"
                 :: "r"(addr), "r"(a), "r"(b), "r"(c), "r"(d) : "memory");
}
__device__ __forceinline__ unsigned long long pack_key(float s, int v) {
    unsigned u = __float_as_uint(s);
    u = (u & 0x80000000u) ? ~u : (u | 0x80000000u);
    return ((unsigned long long)u << 32) | (unsigned)(0xFFFFFFFFu - (unsigned)v);
}
__device__ __forceinline__ uint32_t pack_hl(float v) {
    __nv_bfloat16 h = __float2bfloat16(v);
    float hf = __bfloat162float(h);
    __nv_bfloat16 l = __float2bfloat16(v - hf);
    return ((uint32_t)__bfloat16_as_ushort(l) << 16) | __bfloat16_as_ushort(h);
}

static constexpr int TILE = 128 * 48;      // 6144 B (one plane, 128 rows)
static constexpr int STAGE = 4 * TILE;     // Ah,Al,Bh,Bl = 24576 B
static constexpr int NSTAGE = 4;
static constexpr int GEMM_SMEM = NSTAGE * STAGE + 512;

#define WAITG(n) asm volatile("cp.async.wait_group %0;" :: "n"(n) : "memory")

// ===========================================================================
// WIDE kernel (R7): 128 threads, 4 warps of 64x64, 2 CTAs/SM. MODE 0 only.
//   conv2: A=w2 planes, B=gather f1i, out f2i {hi,lo}+bias+relu
// ===========================================================================
__global__ __launch_bounds__(128, 2) void mma_wide(
    const void* __restrict__ pa0, const void* __restrict__ pa1,
    const void* __restrict__ pb0,
    const float* __restrict__ vec, void* __restrict__ o0, int K)
{
    extern __shared__ char sm[];
    const uint32_t sb = smem_u32(sm);
    const int tid = threadIdx.x, wid = tid >> 5, lane = tid & 31;
    const int m0 = blockIdx.x * 128, n0 = blockIdx.y * 128;
    const int NT = K >> 4;

    float* vecs = (float*)(sm + NSTAGE * STAGE);
    vecs[tid] = vec[m0 + tid];

    const char* dirA_h = (const char*)pa0 + (size_t)(m0 + tid) * 1728 * 2;
    const char* dirA_l = (const char*)pa1 + (size_t)(m0 + tid) * 1728 * 2;
    int n = n0 + tid;
    int bb = n >> 12, rem = n & 4095;
    int oy = rem >> 6, ox = rem & 63;
    const uint32_t* gsrc = (const uint32_t*)pb0 + (size_t)bb * (192u * 128u * 128u);
    int giy0 = 2 * oy - 1, gix0 = 2 * ox - 1;

    const uint32_t loff = (uint32_t)tid * 48;
    uint32_t gregs[16];
    uint32_t gst_hi = 0, gst_lo = 0;

    auto issue = [&](int kt, int s) {
        const uint32_t st = sb + (uint32_t)s * STAGE + loff;
        cp16(st,             dirA_h + kt * 32);
        cp16(st + 16,        dirA_h + kt * 32 + 16);
        cp16(st + TILE,      dirA_l + kt * 32);
        cp16(st + TILE + 16, dirA_l + kt * 32 + 16);
        asm volatile("cp.async.commit_group;" ::: "memory");
        const int k0 = kt * 16;
#pragma unroll
        for (int j = 0; j < 16; j++) {
            int k = k0 + j;
            int ci = (k * 7282) >> 16;
            int r = k - ci * 9;
            int ky = (r * 11) >> 5;
            int kx = r - ky * 3;
            int iy = giy0 + ky, ix = gix0 + kx;
            bool ok = (iy >= 0) && (iy < 128) && (ix >= 0) && (ix < 128);
            gregs[j] = ok ? gsrc[(size_t)((ci * 128 + iy) * 128 + ix)] : 0u;
        }
        gst_hi = st + 2 * TILE;
        gst_lo = gst_hi + TILE;
    };
    auto finish = [&]() {
        sts128(gst_hi,      prmt(gregs[0],  gregs[1],  0x5410), prmt(gregs[2],  gregs[3],  0x5410),
                            prmt(gregs[4],  gregs[5],  0x5410), prmt(gregs[6],  gregs[7],  0x5410));
        sts128(gst_hi + 16, prmt(gregs[8],  gregs[9],  0x5410), prmt(gregs[10], gregs[11], 0x5410),
                            prmt(gregs[12], gregs[13], 0x5410), prmt(gregs[14], gregs[15], 0x5410));
        sts128(gst_lo,      prmt(gregs[0],  gregs[1],  0x7632), prmt(gregs[2],  gregs[3],  0x7632),
                            prmt(gregs[4],  gregs[5],  0x7632), prmt(gregs[6],  gregs[7],  0x7632));
        sts128(gst_lo + 16, prmt(gregs[8],  gregs[9],  0x7632), prmt(gregs[10], gregs[11], 0x7632),
                            prmt(gregs[12], gregs[13], 0x7632), prmt(gregs[14], gregs[15], 0x7632));
    };

    const int wm = wid & 1, wn = wid >> 1;
    const int q = lane >> 3, rr = lane & 7;
    const uint32_t a_off = (uint32_t)((wm * 64 + (q & 1) * 8 + rr) * 48 + (q >> 1) * 16);
    const uint32_t b_off = (uint32_t)(((q >> 1) * 8 + rr) * 48 + (q & 1) * 16)
                         + (uint32_t)(wn * 64) * 48;

    float acc[4][8][4];
#pragma unroll
    for (int i = 0; i < 4; i++)
#pragma unroll
        for (int j = 0; j < 8; j++)
#pragma unroll
            for (int e = 0; e < 4; e++) acc[i][j][e] = 0.f;

    issue(0, 0); finish();
    issue(1, 1); finish();
    issue(2, 2); finish();

#pragma unroll 1
    for (int kt = 0; kt < NT; kt++) {
        if (kt + 2 < NT)      WAITG(2);
        else if (kt + 1 < NT) WAITG(1);
        else                  WAITG(0);
        __syncthreads();

        const int s = kt & 3;
        const uint32_t Ah_b = sb + s * STAGE;
        const uint32_t Al_b = Ah_b + TILE;
        const uint32_t Bh_b = Ah_b + 2 * TILE;
        const uint32_t Bl_b = Ah_b + 3 * TILE;

        uint32_t Bh[4][4], Bl[4][4];
#pragma unroll
        for (int ni = 0; ni < 4; ni++) {
            ldsm4(Bh[ni], Bh_b + b_off + ni * 16 * 48);
            ldsm4(Bl[ni], Bl_b + b_off + ni * 16 * 48);
        }
        const bool doNext = (kt + 3 < NT);
        if (doNext) issue(kt + 3, (kt + 3) & 3);

#pragma unroll
        for (int mi = 0; mi < 4; mi++) {
            uint32_t Ah[4], Al[4];
            ldsm4(Ah, Ah_b + a_off + mi * 768);
            ldsm4(Al, Al_b + a_off + mi * 768);
#pragma unroll
            for (int nj = 0; nj < 8; nj++)
                mma_bf16(acc[mi][nj], Ah, &Bh[nj >> 1][(nj & 1) * 2]);
#pragma unroll
            for (int nj = 0; nj < 8; nj++)
                mma_bf16(acc[mi][nj], Ah, &Bl[nj >> 1][(nj & 1) * 2]);
#pragma unroll
            for (int nj = 0; nj < 8; nj++)
                mma_bf16(acc[mi][nj], Al, &Bh[nj >> 1][(nj & 1) * 2]);
        }
        if (doNext) finish();
    }

    const int tg = lane >> 2, tp = lane & 3;
    uint32_t* Ci = (uint32_t*)o0;
    const int obb = n0 >> 12;
    const int sp0 = (n0 & 4095) + wn * 64;
#pragma unroll
    for (int mi = 0; mi < 4; mi++)
#pragma unroll
        for (int h = 0; h < 2; h++) {
            int ml = wm * 64 + mi * 16 + tg + h * 8;
            int m = m0 + ml;
            float bv = vecs[ml];
            uint32_t* rowp = Ci + ((size_t)obb * 384 + m) * 4096;
#pragma unroll
            for (int nj = 0; nj < 8; nj++) {
                float v0 = fmaxf(acc[mi][nj][h * 2 + 0] + bv, 0.f);
                float v1 = fmaxf(acc[mi][nj][h * 2 + 1] + bv, 0.f);
                *(uint2*)(rowp + sp0 + nj * 8 + 2 * tp) =
                    make_uint2(pack_hl(v0), pack_hl(v1));
            }
        }
}

// ===========================================================================
// NARROW kernel (R5): 256 threads, 8 warps of 64x32, 2 CTAs/SM (16 warps).
//  MODE 1: conv3  A=gather f2i, B=w3 planes, out f3 planes + bias
//  MODE 2: dist   A=f3 planes,  B=cb planes, fused argmax
// ===========================================================================
template<int MODE>
__global__ __launch_bounds__(256, 2) void mma_narrow(
    const void* __restrict__ pa0, const void* __restrict__ pa1,
    const void* __restrict__ pb0, const void* __restrict__ pb1,
    const float* __restrict__ vec, void* __restrict__ o0,
    void* __restrict__ o1, int K)
{
    extern __shared__ char sm[];
    const uint32_t sb = smem_u32(sm);
    const int tid = threadIdx.x, wid = tid >> 5, lane = tid & 31;
    const int m0 = blockIdx.x * 128, n0 = blockIdx.y * 128;
    const int NT = K >> 4;

    float* vecs = (float*)(sm + NSTAGE * STAGE);
    if (tid < 128) vecs[tid] = vec[n0 + tid];

    const int lrow = tid >> 1, lhalf = tid & 1;

    const char* dirA_h = nullptr; const char* dirA_l = nullptr;
    const char* dirB_h = nullptr; const char* dirB_l = nullptr;
    const uint32_t* gsrc = nullptr;
    int giy0 = 0, gix0 = 0;

    if constexpr (MODE == 1) {
        int n = m0 + lrow;
        int bb = n >> 10, rem = n & 1023;
        int oy = rem >> 5, ox = rem & 31;
        gsrc = (const uint32_t*)pa0 + (size_t)bb * (384u * 64u * 64u);
        giy0 = 2 * oy - 1; gix0 = 2 * ox - 1;
        dirB_h = (const char*)pb0 + ((size_t)(n0 + lrow) * 3456 + lhalf * 8) * 2;
        dirB_l = (const char*)pb1 + ((size_t)(n0 + lrow) * 3456 + lhalf * 8) * 2;
    } else {
        dirA_h = (const char*)pa0 + ((size_t)(m0 + lrow) * 768 + lhalf * 8) * 2;
        dirA_l = (const char*)pa1 + ((size_t)(m0 + lrow) * 768 + lhalf * 8) * 2;
        dirB_h = (const char*)pb0 + ((size_t)(n0 + lrow) * 768 + lhalf * 8) * 2;
        dirB_l = (const char*)pb1 + ((size_t)(n0 + lrow) * 768 + lhalf * 8) * 2;
    }

    const uint32_t loff = (uint32_t)(lrow * 48 + lhalf * 16);

    auto gather8 = [&](int kt, uint32_t dhi, uint32_t dlo) {
        uint32_t e[8];
        const int k0 = kt * 16 + lhalf * 8;
#pragma unroll
        for (int j = 0; j < 8; j++) {
            int k = k0 + j;
            int ci = (k * 7282) >> 16;
            int r = k - ci * 9;
            int ky = (r * 11) >> 5;
            int kx = r - ky * 3;
            int iy = giy0 + ky, ix = gix0 + kx;
            bool ok = (iy >= 0) && (iy < 64) && (ix >= 0) && (ix < 64);
            e[j] = ok ? gsrc[(size_t)((ci * 64 + iy) * 64 + ix)] : 0u;
        }
        sts128(dhi, prmt(e[0], e[1], 0x5410), prmt(e[2], e[3], 0x5410),
                    prmt(e[4], e[5], 0x5410), prmt(e[6], e[7], 0x5410));
        sts128(dlo, prmt(e[0], e[1], 0x7632), prmt(e[2], e[3], 0x7632),
                    prmt(e[4], e[5], 0x7632), prmt(e[6], e[7], 0x7632));
    };

    auto load_chunk = [&](int kt, int s) {
        const uint32_t st = sb + s * STAGE + loff;
        if constexpr (MODE == 1) {
            gather8(kt, st, st + TILE);
            cp16(st + 2 * TILE, dirB_h + kt * 32);
            cp16(st + 3 * TILE, dirB_l + kt * 32);
        } else {
            cp16(st,            dirA_h + kt * 32);
            cp16(st + TILE,     dirA_l + kt * 32);
            cp16(st + 2 * TILE, dirB_h + kt * 32);
            cp16(st + 3 * TILE, dirB_l + kt * 32);
        }
        asm volatile("cp.async.commit_group;" ::: "memory");
    };

    const int wm = wid & 1, wn = wid >> 1;
    const int q = lane >> 3, rr = lane & 7;
    const uint32_t a_off = (uint32_t)((wm * 64 + (q & 1) * 8 + rr) * 48 + (q >> 1) * 16);
    const uint32_t b_off = (uint32_t)(((q >> 1) * 8 + rr) * 48 + (q & 1) * 16)
                         + (uint32_t)(wn * 32) * 48;

    float acc[4][4][4];
#pragma unroll
    for (int i = 0; i < 4; i++)
#pragma unroll
        for (int j = 0; j < 4; j++)
#pragma unroll
            for (int e = 0; e < 4; e++) acc[i][j][e] = 0.f;

    load_chunk(0, 0);
    load_chunk(1, 1);
    load_chunk(2, 2);

#pragma unroll 1
    for (int kt = 0; kt < NT; kt++) {
        if (kt + 2 < NT)      WAITG(2);
        else if (kt + 1 < NT) WAITG(1);
        else                  WAITG(0);
        __syncthreads();

        const int s = kt & 3;
        const uint32_t Ah_b = sb + s * STAGE;
        const uint32_t Al_b = Ah_b + TILE;
        const uint32_t Bh_b = Ah_b + 2 * TILE;
        const uint32_t Bl_b = Ah_b + 3 * TILE;

        uint32_t Bh[2][4], Bl[2][4];
        ldsm4(Bh[0], Bh_b + b_off);
        ldsm4(Bh[1], Bh_b + b_off + 16 * 48);
        ldsm4(Bl[0], Bl_b + b_off);
        ldsm4(Bl[1], Bl_b + b_off + 16 * 48);
#pragma unroll
        for (int mi = 0; mi < 4; mi++) {
            uint32_t Ah[4], Al[4];
            ldsm4(Ah, Ah_b + a_off + mi * 768);
            ldsm4(Al, Al_b + a_off + mi * 768);
#pragma unroll
            for (int nj = 0; nj < 4; nj++)
                mma_bf16(acc[mi][nj], Ah, &Bh[nj >> 1][(nj & 1) * 2]);
#pragma unroll
            for (int nj = 0; nj < 4; nj++)
                mma_bf16(acc[mi][nj], Ah, &Bl[nj >> 1][(nj & 1) * 2]);
#pragma unroll
            for (int nj = 0; nj < 4; nj++)
                mma_bf16(acc[mi][nj], Al, &Bh[nj >> 1][(nj & 1) * 2]);
        }

        if (kt + 3 < NT) load_chunk(kt + 3, (kt + 3) & 3);
    }

    const int tg = lane >> 2, tp = lane & 3;

    if constexpr (MODE == 1) {
        __nv_bfloat16* fh = (__nv_bfloat16*)o0;
        __nv_bfloat16* fl = (__nv_bfloat16*)o1;
#pragma unroll
        for (int mi = 0; mi < 4; mi++)
#pragma unroll
            for (int h = 0; h < 2; h++) {
                int m = m0 + wm * 64 + mi * 16 + tg + h * 8;   // token
                __nv_bfloat16* rowh = fh + (size_t)m * 768 + n0;
                __nv_bfloat16* rowl = fl + (size_t)m * 768 + n0;
#pragma unroll
                for (int nj = 0; nj < 4; nj++) {
                    int nl = wn * 32 + nj * 8 + 2 * tp;
                    float v0 = acc[mi][nj][h * 2 + 0] + vecs[nl + 0];
                    float v1 = acc[mi][nj][h * 2 + 1] + vecs[nl + 1];
                    __nv_bfloat16 h0 = __float2bfloat16(v0);
                    __nv_bfloat16 h1 = __float2bfloat16(v1);
                    __nv_bfloat16 l0 = __float2bfloat16(v0 - __bfloat162float(h0));
                    __nv_bfloat16 l1 = __float2bfloat16(v1 - __bfloat162float(h1));
                    *(__nv_bfloat162*)(rowh + nl) = __nv_bfloat162(h0, h1);
                    *(__nv_bfloat162*)(rowl + nl) = __nv_bfloat162(l0, l1);
                }
            }
    } else {
#pragma unroll
        for (int mi = 0; mi < 4; mi++)
#pragma unroll
            for (int h = 0; h < 2; h++) {
                int m = m0 + wm * 64 + mi * 16 + tg + h * 8;   // token
                unsigned long long best = 0ull;
#pragma unroll
                for (int nj = 0; nj < 4; nj++)
#pragma unroll
                    for (int e = 0; e < 2; e++) {
                        int nl = wn * 32 + nj * 8 + 2 * tp + e;
                        float sc = acc[mi][nj][h * 2 + e] - vecs[nl];
                        unsigned long long key = pack_key(sc, n0 + nl);
                        best = key > best ? key : best;
                    }
                unsigned long long o = __shfl_xor_sync(0xFFFFFFFFu, best, 1);
                best = best > o ? best : o;
                o = __shfl_xor_sync(0xFFFFFFFFu, best, 2);
                best = best > o ? best : o;
                if (tp == 0) atomicMax(&g_best[m], best);
            }
    }
}

// ---------------------------------------------------------------------------
// conv1: Cin=3, 3x3 s2 pad1, relu -> interleaved {hi,lo} uint32 NCHW
// ---------------------------------------------------------------------------
__global__ __launch_bounds__(128) void conv1_kernel(
    const float* __restrict__ in, const float* __restrict__ w,
    const float* __restrict__ bias)
{
    __shared__ float Ws[192 * 27];
    __shared__ float Bsm[192];
    for (int i = threadIdx.x; i < 192 * 27; i += 128) Ws[i] = w[i];
    for (int i = threadIdx.x; i < 192; i += 128) Bsm[i] = bias[i];
    __syncthreads();

    int g = blockIdx.x * 128 + threadIdx.x;
    int x0 = (g & 31) * 4;
    int y = (g >> 5) & 127;
    int b = g >> 12;

    float xv[3][3][9];
    int iy0 = 2 * y - 1;
    int ix0 = 2 * x0 - 1;
#pragma unroll
    for (int ci = 0; ci < 3; ci++)
#pragma unroll
        for (int ky = 0; ky < 3; ky++) {
            int iy = iy0 + ky;
            bool yok = (iy >= 0) && (iy < 256);
            const float* rowp = in + (((size_t)b * 3 + ci) * 256 + iy) * 256;
#pragma unroll
            for (int c = 0; c < 9; c++) {
                int ix = ix0 + c;
                xv[ci][ky][c] = (yok && ix >= 0 && ix < 256) ? rowp[ix] : 0.f;
            }
        }

    uint32_t* outp = g_f1i + (size_t)b * 192 * 16384 + y * 128 + x0;
    for (int co = 0; co < 192; co++) {
        float bv = Bsm[co];
        float a0 = bv, a1 = bv, a2 = bv, a3 = bv;
        const float* wp = &Ws[co * 27];
#pragma unroll
        for (int ci = 0; ci < 3; ci++)
#pragma unroll
            for (int ky = 0; ky < 3; ky++)
#pragma unroll
                for (int kx = 0; kx < 3; kx++) {
                    float wv = wp[ci * 9 + ky * 3 + kx];
                    a0 = fmaf(wv, xv[ci][ky][0 + kx], a0);
                    a1 = fmaf(wv, xv[ci][ky][2 + kx], a1);
                    a2 = fmaf(wv, xv[ci][ky][4 + kx], a2);
                    a3 = fmaf(wv, xv[ci][ky][6 + kx], a3);
                }
        uint4 r;
        r.x = pack_hl(fmaxf(a0, 0.f));
        r.y = pack_hl(fmaxf(a1, 0.f));
        r.z = pack_hl(fmaxf(a2, 0.f));
        r.w = pack_hl(fmaxf(a3, 0.f));
        *(uint4*)(outp + (size_t)co * 16384) = r;
    }
}

// ---------------------------------------------------------------------------
static constexpr int N_W2 = 384 * 1728;
static constexpr int N_W3 = 768 * 3456;
static constexpr int N_CB = 8192 * 768;

__global__ void cvt_all_kernel(const float* __restrict__ w2,
                               const float* __restrict__ w3,
                               const float* __restrict__ cb)
{
    int i = blockIdx.x * 256 + threadIdx.x;
    const float* src; __nv_bfloat16 *hi, *lo; int idx;
    if (i < N_W2) { src = w2; hi = g_w2h; lo = g_w2l; idx = i; }
    else if (i < N_W2 + N_W3) { src = w3; hi = g_w3h; lo = g_w3l; idx = i - N_W2; }
    else if (i < N_W2 + N_W3 + N_CB) { src = cb; hi = g_cbh; lo = g_cbl; idx = i - N_W2 - N_W3; }
    else return;
    float v = src[idx];
    __nv_bfloat16 h = __float2bfloat16(v);
    hi[idx] = h;
    lo[idx] = __float2bfloat16(v - __bfloat162float(h));
}

// c2half + g_best init fused
__global__ void c2half_kernel(const float* __restrict__ cb) {
    int gt = blockIdx.x * 256 + threadIdx.x;
    if (gt < 16384) g_best[gt] = 0ULL;
    int v = blockIdx.x * 8 + (threadIdx.x >> 5);
    int lane = threadIdx.x & 31;
    const float* row = cb + (size_t)v * 768;
    float s = 0.f;
    for (int c = lane; c < 768; c += 32) { float t = row[c]; s = fmaf(t, t, s); }
#pragma unroll
    for (int o = 16; o > 0; o >>= 1) s += __shfl_xor_sync(0xFFFFFFFFu, s, o);
    if (lane == 0) g_c2h[v] = 0.5f * s;
}

__global__ __launch_bounds__(192) void output_kernel(
    const float* __restrict__ table, float* __restrict__ out)
{
    int p = blockIdx.x;
    unsigned long long key = g_best[p];
    unsigned v = 0xFFFFFFFFu - (unsigned)(key & 0xFFFFFFFFu);
    if (threadIdx.x == 0) out[p] = (float)v;
    float4* dst = (float4*)(out + 16384 + (size_t)p * 768);
    const float4* src = (const float4*)(table + (size_t)v * 768);
    dst[threadIdx.x] = src[threadIdx.x];
}

// ---------------------------------------------------------------------------
extern "C" void kernel_launch(void* const* d_in, const int* in_sizes, int n_in,
                              void* d_out, int out_size)
{
    (void)in_sizes; (void)n_in; (void)out_size;
    const float* image = (const float*)d_in[0];
    const float* w1 = (const float*)d_in[1];
    const float* b1 = (const float*)d_in[2];
    const float* w2 = (const float*)d_in[3];
    const float* b2 = (const float*)d_in[4];
    const float* w3 = (const float*)d_in[5];
    const float* b3 = (const float*)d_in[6];
    const float* cb = (const float*)d_in[7];
    const float* tab = (const float*)d_in[8];
    float* out = (float*)d_out;

    void *pf1, *pf2, *pf3h, *pf3l, *pw2h, *pw2l, *pw3h, *pw3l, *pcbh, *pcbl, *pc2;
    cudaGetSymbolAddress(&pf1, g_f1i);
    cudaGetSymbolAddress(&pf2, g_f2i);
    cudaGetSymbolAddress(&pf3h, g_f3h);
    cudaGetSymbolAddress(&pf3l, g_f3l);
    cudaGetSymbolAddress(&pw2h, g_w2h);
    cudaGetSymbolAddress(&pw2l, g_w2l);
    cudaGetSymbolAddress(&pw3h, g_w3h);
    cudaGetSymbolAddress(&pw3l, g_w3l);
    cudaGetSymbolAddress(&pcbh, g_cbh);
    cudaGetSymbolAddress(&pcbl, g_cbl);
    cudaGetSymbolAddress(&pc2, g_c2h);

    cudaFuncSetAttribute(mma_wide, cudaFuncAttributeMaxDynamicSharedMemorySize, GEMM_SMEM);
    cudaFuncSetAttribute(mma_narrow<1>, cudaFuncAttributeMaxDynamicSharedMemorySize, GEMM_SMEM);
    cudaFuncSetAttribute(mma_narrow<2>, cudaFuncAttributeMaxDynamicSharedMemorySize, GEMM_SMEM);

    c2half_kernel<<<1024, 256>>>(cb);
    cvt_all_kernel<<<(N_W2 + N_W3 + N_CB + 255) / 256, 256>>>(w2, w3, cb);
    conv1_kernel<<<512, 128>>>(image, w1, b1);

    // conv2 (WIDE): M=384 (w2 rows), N=65536 (spatial), K=1728
    mma_wide<<<dim3(3, 512), 128, GEMM_SMEM>>>(pw2h, pw2l, pf1, b2, pf2, 1728);
    // conv3 (NARROW): M=16384 (tokens, gathered), N=768 (w3 rows), K=3456
    mma_narrow<1><<<dim3(128, 6), 256, GEMM_SMEM>>>(
        pf2, nullptr, pw3h, pw3l, b3, pf3h, pf3l, 3456);
    // distance (NARROW): M=16384 (tokens), N=8192 (codes), K=768, fused argmax
    mma_narrow<2><<<dim3(128, 64), 256, GEMM_SMEM>>>(
        pf3h, pf3l, pcbh, pcbl, (const float*)pc2, nullptr, nullptr, 768);

    output_kernel<<<16384, 192>>>(tab, out);
}